// round 1
// baseline (speedup 1.0000x reference)
#include <cuda_runtime.h>
#include <cstddef>

#define FULLMASK 0xffffffffu

// DEFAULT_U_A = log(e - 1 - 0.001)
#define UA_CONST 0.54074271f
#define SCL (1.0f/1000.0f)

// One batch element per 16-lane group; 2 elements per warp; 16 per block.
__global__ __launch_bounds__(256)
void dsit_kernel(const float* __restrict__ x,
                 const float* __restrict__ h,
                 float* __restrict__ z_out,
                 float* __restrict__ ld_out,
                 int batch)
{
    // u matrix per element, row stride 20 floats (pad: conflict-free float4 STS)
    __shared__ __align__(16) float u_sh[16][16 * 20];

    const int tid = threadIdx.x;
    const int e   = tid >> 4;     // element slot within block
    const int o   = tid & 15;     // row index this lane owns
    int b = blockIdx.x * 16 + e;
    if (b >= batch) b = batch - 1;   // duplicate-work clamp (keeps warp convergent)

    const float* hb = h + (size_t)b * 544;

    // ---- x value owned by this lane ----
    const float xv = x[(size_t)b * 16 + o];

    // ---- u = softmax(du_row_o / 1000) ; du at offset 288 + o*16 ----
    float uu[16];
    {
        const float4* p4 = reinterpret_cast<const float4*>(hb + 288 + o * 16);
        float4 v[4];
        v[0] = p4[0]; v[1] = p4[1]; v[2] = p4[2]; v[3] = p4[3];
        const float* vf = reinterpret_cast<const float*>(v);
        float s = 0.f;
#pragma unroll
        for (int i = 0; i < 16; i++) { uu[i] = __expf(vf[i] * SCL); s += uu[i]; }
        const float rs = __fdividef(1.f, s);
#pragma unroll
        for (int i = 0; i < 16; i++) uu[i] *= rs;
    }

    // ---- w = softmax(dw_row_o / 1000) ; dw at offset 32 + o*16 ----
    float ww[16];
    {
        const float4* p4 = reinterpret_cast<const float4*>(hb + 32 + o * 16);
        float4 v[4];
        v[0] = p4[0]; v[1] = p4[1]; v[2] = p4[2]; v[3] = p4[3];
        const float* vf = reinterpret_cast<const float*>(v);
        float s = 0.f;
#pragma unroll
        for (int i = 0; i < 16; i++) { ww[i] = __expf(vf[i] * SCL); s += ww[i]; }
        const float rs = __fdividef(1.f, s);
#pragma unroll
        for (int i = 0; i < 16; i++) ww[i] *= rs;
    }

    // ---- a, b scalars for this lane's o ----
    const float da = hb[o];
    const float db = hb[16 + o];
    const float t  = UA_CONST + da * SCL;
    const float av = __logf(1.f + __expf(t)) + 0.001f;   // softplus + MIN_SCALE
    const float bv = db * SCL;

    // ---- ux[o] = u_row_o . x  (x gathered via shuffle) ----
    float ux = 0.f;
#pragma unroll
    for (int i = 0; i < 16; i++)
        ux = fmaf(uu[i], __shfl_sync(FULLMASK, xv, i, 16), ux);

    // ---- c = sigmoid(a*ux + b) ----
    const float pre = fmaf(av, ux, bv);
    const float cc  = __fdividef(1.f, 1.f + __expf(-pre));

    // ---- p = a * sigmoid(c) * (1 - sigmoid(c))   [note: sigmoid OF c] ----
    const float q  = __fdividef(1.f, 1.f + __expf(-cc));
    const float pv = av * q * (1.f - q);

    // ---- store u row to shared for the M matmul ----
    {
        float* su = &u_sh[e][o * 20];
        reinterpret_cast<float4*>(su)[0] = make_float4(uu[0], uu[1], uu[2], uu[3]);
        reinterpret_cast<float4*>(su)[1] = make_float4(uu[4], uu[5], uu[6], uu[7]);
        reinterpret_cast<float4*>(su)[2] = make_float4(uu[8], uu[9], uu[10], uu[11]);
        reinterpret_cast<float4*>(su)[3] = make_float4(uu[12], uu[13], uu[14], uu[15]);
    }

    // ---- d[o] = w_row_o . c ;  wp[j] = w[o,j]*p[j] ----
    float dv = 0.f;
#pragma unroll
    for (int j = 0; j < 16; j++) {
        const float cj = __shfl_sync(FULLMASK, cc, j, 16);
        const float pj = __shfl_sync(FULLMASK, pv, j, 16);
        dv = fmaf(ww[j], cj, dv);
        ww[j] *= pj;                    // ww becomes wp
    }
    const float zv = __logf(dv) - __logf(1.f - dv);

    __syncwarp(FULLMASK);               // u_sh producer/consumer within warp

    // ---- M row o:  M[o,i] = sum_j wp[j] * u_sh[j][i] ----
    float acc[16];
#pragma unroll
    for (int i = 0; i < 16; i++) acc[i] = 0.f;

    const float* ue = u_sh[e];
#pragma unroll
    for (int j = 0; j < 16; j++) {
        const float wj = ww[j];
        const float4* r = reinterpret_cast<const float4*>(ue + j * 20);
        const float4 r0 = r[0], r1 = r[1], r2 = r[2], r3 = r[3];
        acc[0]  = fmaf(wj, r0.x, acc[0]);  acc[1]  = fmaf(wj, r0.y, acc[1]);
        acc[2]  = fmaf(wj, r0.z, acc[2]);  acc[3]  = fmaf(wj, r0.w, acc[3]);
        acc[4]  = fmaf(wj, r1.x, acc[4]);  acc[5]  = fmaf(wj, r1.y, acc[5]);
        acc[6]  = fmaf(wj, r1.z, acc[6]);  acc[7]  = fmaf(wj, r1.w, acc[7]);
        acc[8]  = fmaf(wj, r2.x, acc[8]);  acc[9]  = fmaf(wj, r2.y, acc[9]);
        acc[10] = fmaf(wj, r2.z, acc[10]); acc[11] = fmaf(wj, r2.w, acc[11]);
        acc[12] = fmaf(wj, r3.x, acc[12]); acc[13] = fmaf(wj, r3.y, acc[13]);
        acc[14] = fmaf(wj, r3.z, acc[14]); acc[15] = fmaf(wj, r3.w, acc[15]);
    }

    // ---- per-lane contribution: 16*z[o] + sum_i log M[o,i] ----
    float contrib = 16.f * zv;
#pragma unroll
    for (int i = 0; i < 16; i++) contrib += __logf(acc[i]);

    // ---- reduce across 16-lane group ----
#pragma unroll
    for (int m = 8; m >= 1; m >>= 1)
        contrib += __shfl_xor_sync(FULLMASK, contrib, m, 16);

    // ---- outputs ----
    z_out[(size_t)b * 16 + o] = zv;
    if (o == 0) ld_out[b] = contrib;
}

extern "C" void kernel_launch(void* const* d_in, const int* in_sizes, int n_in,
                              void* d_out, int out_size)
{
    const float* x = (const float*)d_in[0];   // [B, 16]
    const float* h = (const float*)d_in[1];   // [B, 544]
    const int batch = in_sizes[0] / 16;

    float* z_out  = (float*)d_out;                      // [B,16]
    float* ld_out = z_out + (size_t)batch * 16;         // [B]

    const int blocks = (batch + 15) / 16;
    dsit_kernel<<<blocks, 256>>>(x, h, z_out, ld_out, batch);
}